// round 14
// baseline (speedup 1.0000x reference)
#include <cuda_runtime.h>
#include <cuda_fp16.h>
#include <cstdint>

#define DM 256
#define DF 1024
#define NE 4
#define NT 65536

// word (=4B=half2) pitches; pair-interleaved layouts make every operand
// fetch an LDS.64 with bank-pair pattern 4g+t (conflict-free per phase):
//  pitch/2 % 16 == 4  ->  XPW=136, B1PW=136, HPW=40, B2PW=40
#define XPW  136   // X  [128 r][128 kw]
#define B1PW 136   // B1 [32 n][128 kw]
#define B2PW 40    // B2 [256 n][16 kw]
#define HPW  40    // H  [128 r][16 kw]

#define B1BUF 4352    // words per B1 buffer (32*136)
#define B2BUF 10240   // words per B2 buffer (256*40)

// word offsets in dynamic smem
#define SM_XS  0                        // 128*136 = 17408
#define SM_B1  17408                    // 2 x 4352
#define SM_B2  26112                    // 2 x 10240
#define SM_HS  46592                    // 128*40 = 5120
#define SM_BS1 51712                    // 1024 fp32
#define SM_BS2 52736                    // 256 fp32
#define SM_TOK 52992                    // 128 int
#define SM_WORDS 53120
#define SM_BYTES (SM_WORDS * 4)         // 212480 bytes (<= 227 KB cap)

__device__ int      g_cnt[NE];
__device__ int      g_list[NE * NT];
__device__ unsigned g_w1p[NE * DF * 128];  // [e][ff n][kw] pair-interleaved half2
__device__ unsigned g_w2p[NE * DM * 512];  // [e][dm n][kw] pair-interleaved half2

__device__ __forceinline__ unsigned f2h2(float lo, float hi) {
    __half2 h = __floats2half2_rn(lo, hi);
    return *reinterpret_cast<unsigned*>(&h);
}

__device__ __forceinline__ void cp16(void* s, const void* g) {
    uint32_t sa = (uint32_t)__cvta_generic_to_shared(s);
    asm volatile("cp.async.cg.shared.global [%0], [%1], 16;" :: "r"(sa), "l"(g));
}

#define CP_COMMIT() asm volatile("cp.async.commit_group;")
#define CP_WAIT0()  asm volatile("cp.async.wait_group 0;")

// D += A*B for m16n8k16 fp16 inputs, fp32 accumulate
#define MMA16(d, a, b0, b1)                                                  \
    asm volatile(                                                            \
        "mma.sync.aligned.m16n8k16.row.col.f32.f16.f16.f32 "                 \
        "{%0,%1,%2,%3},{%4,%5,%6,%7},{%8,%9},{%0,%1,%2,%3};"                 \
        : "+f"((d)[0]), "+f"((d)[1]), "+f"((d)[2]), "+f"((d)[3])             \
        : "r"((a)[0]), "r"((a)[1]), "r"((a)[2]), "r"((a)[3]),                \
          "r"(b0), "r"(b1))

// interleave map: q -> s = 2*(q&3) + (q>>2) within each 8-word block
__device__ __forceinline__ int smap(int w) {
    return (w & ~7) + 2 * (w & 3) + ((w & 7) >> 2);
}

// ---------------- prep kernels ----------------

// launch 0: zero inactive output rows + zero counters
__global__ void zero_inactive_cnt_k(const int* __restrict__ b_seq,
                                    float4* __restrict__ out4) {
    if (blockIdx.x == 0 && threadIdx.x < NE) g_cnt[threadIdx.x] = 0;
    int w = (blockIdx.x * blockDim.x + threadIdx.x) >> 5;
    int lane = threadIdx.x & 31;
    if (b_seq[w] == 0) {
        float4 z = make_float4(0.f, 0.f, 0.f, 0.f);
        out4[(size_t)w * 64 + lane] = z;
        out4[(size_t)w * 64 + 32 + lane] = z;
    }
}

// launch 1
__global__ void build_lists_k(const int* __restrict__ b_seq) {
    int t = blockIdx.x * blockDim.x + threadIdx.x;
    if (t < NT) {
        int b = b_seq[t];
        if (b > 0) {
            int p = atomicAdd(&g_cnt[b - 1], 1);
            g_list[(b - 1) * NT + p] = t;
        }
    }
}

// launch 2: pack W1/W2 -> half2, k-pair-interleaved, n-major rows
__global__ void prep_pack_k(const float* __restrict__ W1,
                            const float* __restrict__ W2) {
    int id = blockIdx.x * blockDim.x + threadIdx.x;
    const int N1 = NE * 128 * DF;            // w1 words
    if (id < N1) {
        int n = id % DF;
        int r = id / DF;
        int kpos = r % 128, e = r / 128;
        int s = kpos & 7;
        int kp = (kpos & ~7) + (s >> 1) + ((s & 1) << 2);
        const float* w1e = W1 + (size_t)e * DM * DF;
        float lo = w1e[(size_t)(2 * kp) * DF + n];
        float hi = w1e[(size_t)(2 * kp + 1) * DF + n];
        g_w1p[((size_t)e * DF + n) * 128 + kpos] = f2h2(lo, hi);
    } else {
        int id2 = id - N1;
        if (id2 < NE * 512 * DM) {
            int n = id2 % DM;
            int r = id2 / DM;
            int kpos = r % 512, e = r / 512;
            int s = kpos & 7;
            int kp = (kpos & ~7) + (s >> 1) + ((s & 1) << 2);
            const float* w2e = W2 + (size_t)e * DF * DM;
            float lo = w2e[(size_t)(2 * kp) * DM + n];
            float hi = w2e[(size_t)(2 * kp + 1) * DM + n];
            g_w2p[((size_t)e * DM + n) * 512 + kpos] = f2h2(lo, hi);
        }
    }
}

// ---------------- main fused grouped FFN kernel (launch 3) ----------------
// 1 CTA = 128 tokens of one expert, 256 threads = 8 warps. FP16 operands
// (same 11-bit mantissa as tf32), fp32 accumulate, m16n8k16 MMA.
// Double-buffered B1/B2: loads for chunk fc+1 issued right after the
// top-of-chunk sync into the idle buffer -> only 2 __syncthreads per chunk
// and a single cp.async wait point (vs 4 syncs + 2 waits before).

__global__ __launch_bounds__(256, 1)
void pff_main_k(const float* __restrict__ x,
                const float* __restrict__ b1g,
                const float* __restrict__ b2g,
                float* __restrict__ out) {
    extern __shared__ unsigned smw[];
    unsigned* XSW = smw + SM_XS;
    unsigned* B1W = smw + SM_B1;
    unsigned* B2W = smw + SM_B2;
    unsigned* HSW = smw + SM_HS;
    float*    BS1 = (float*)(smw + SM_BS1);
    float*    BS2 = (float*)(smw + SM_BS2);
    int*      TOK = (int*)(smw + SM_TOK);

    // resolve (expert, segment)
    int bid = blockIdx.x;
    int e = -1, seg = 0, cnt = 0, acc = 0;
#pragma unroll
    for (int i = 0; i < NE; i++) {
        int ci = g_cnt[i];
        int nt = (ci + 127) >> 7;
        if (e < 0 && bid < acc + nt) { e = i; seg = bid - acc; cnt = ci; }
        acc += nt;
    }
    if (e < 0) return;

    int tid = threadIdx.x;

    if (tid < 128) {
        int idx = seg * 128 + tid;
        TOK[tid] = (idx < cnt) ? g_list[e * NT + idx] : -1;
    }
    // biases into smem (fp32)
#pragma unroll
    for (int q = 0; q < 4; q++) BS1[q * 256 + tid] = b1g[e * DF + q * 256 + tid];
    BS2[tid] = b2g[e * DM + tid];
    __syncthreads();

    // gather X rows -> fp16, pair-interleaved; padded rows = 0
    for (int i = tid; i < 128 * 64; i += 256) {
        int r = i >> 6, c4 = i & 63;
        int tk = TOK[r];
        float4 v = make_float4(0.f, 0.f, 0.f, 0.f);
        if (tk >= 0) v = reinterpret_cast<const float4*>(x)[(size_t)tk * 64 + c4];
        int w0 = 2 * c4;
        XSW[r * XPW + smap(w0)]     = f2h2(v.x, v.y);
        XSW[r * XPW + smap(w0 + 1)] = f2h2(v.z, v.w);
    }

    const unsigned* w1p = g_w1p + (size_t)e * DF * 128;
    const unsigned* w2p = g_w2p + (size_t)e * DM * 512;

    // combined B1+B2 chunk loader into buffer (fc&1); one commit group
    auto issue = [&](int fc) {
        if (fc < 32) {
            unsigned* B1d = B1W + (fc & 1) * B1BUF;
            unsigned* B2d = B2W + (fc & 1) * B2BUF;
#pragma unroll
            for (int q = 0; q < 4; q++) {
                int i = q * 256 + tid;           // 0..1023
                int n = i >> 5, j = i & 31;
                cp16(&B1d[n * B1PW + j * 4],
                     w1p + ((size_t)(fc * 32 + n)) * 128 + j * 4);
            }
#pragma unroll
            for (int q = 0; q < 4; q++) {
                int i = q * 256 + tid;           // 0..1023
                int n = i >> 2, j = i & 3;
                cp16(&B2d[n * B2PW + j * 4],
                     w2p + (size_t)n * 512 + fc * 16 + j * 4);
            }
        }
        CP_COMMIT();
    };

    int w = tid >> 5, lane = tid & 31;
    int wm = w & 3, wn = w >> 2;        // GEMM1: 4M x 2N
    int wm2 = w & 1, wn4 = w >> 1;      // GEMM2: 2M x 4N
    int g = lane >> 2, t = lane & 3;

    // Y accumulator: per warp 64 rows x 64 cols -> y[4][8][4] = 128 regs
    float y[4][8][4];
#pragma unroll
    for (int ms = 0; ms < 4; ms++)
#pragma unroll
        for (int ns = 0; ns < 8; ns++)
#pragma unroll
            for (int q = 0; q < 4; q++) y[ms][ns][q] = 0.f;

    issue(0);

    for (int fc = 0; fc < 32; fc++) {
        CP_WAIT0();            // B(fc) landed (only outstanding group)
        __syncthreads();       // B(fc)+X visible; all warps past GEMM2(fc-1)
        issue(fc + 1);         // prefetch into idle buffer during this chunk

        const unsigned* B1c = B1W + (fc & 1) * B1BUF;
        const unsigned* B2c = B2W + (fc & 1) * B2BUF;

        // ---- GEMM1: H32[128x32] = X[128x256] @ W1[:, fc*32:+32] ----
        float h[2][2][4];
#pragma unroll
        for (int ms = 0; ms < 2; ms++)
#pragma unroll
            for (int ns = 0; ns < 2; ns++)
#pragma unroll
                for (int q = 0; q < 4; q++) h[ms][ns][q] = 0.f;

#pragma unroll
        for (int it = 0; it < 16; it++) {      // k16 steps over K=256
            int base = it * 8;
            unsigned a[2][4];
#pragma unroll
            for (int ms = 0; ms < 2; ms++) {
                int r = wm * 32 + ms * 16 + g;
                uint2 u = *reinterpret_cast<const uint2*>(&XSW[r * XPW + base + 2 * t]);
                uint2 v = *reinterpret_cast<const uint2*>(&XSW[(r + 8) * XPW + base + 2 * t]);
                a[ms][0] = u.x; a[ms][1] = v.x; a[ms][2] = u.y; a[ms][3] = v.y;
            }
#pragma unroll
            for (int ns = 0; ns < 2; ns++) {
                int n = wn * 16 + ns * 8 + g;
                uint2 bb = *reinterpret_cast<const uint2*>(&B1c[n * B1PW + base + 2 * t]);
                MMA16(h[0][ns], a[0], bb.x, bb.y);
                MMA16(h[1][ns], a[1], bb.x, bb.y);
            }
        }

        // ---- relu + b1 -> HS (fp16, pair-interleaved) ----
#pragma unroll
        for (int ms = 0; ms < 2; ms++) {
            int r = wm * 32 + ms * 16 + g;
#pragma unroll
            for (int ns = 0; ns < 2; ns++) {
                int col = wn * 16 + ns * 8 + 2 * t;
                float bb0 = BS1[fc * 32 + col];
                float bb1 = BS1[fc * 32 + col + 1];
                int pos = wn * 8 + 2 * t + ns;   // interleaved word position
                HSW[r * HPW + pos] =
                    f2h2(fmaxf(h[ms][ns][0] + bb0, 0.f),
                         fmaxf(h[ms][ns][1] + bb1, 0.f));
                HSW[(r + 8) * HPW + pos] =
                    f2h2(fmaxf(h[ms][ns][2] + bb0, 0.f),
                         fmaxf(h[ms][ns][3] + bb1, 0.f));
            }
        }
        __syncthreads();       // H visible to all warps

        // ---- GEMM2 (2M x 4N): Y[128x256] += relu(H32) @ W2[fc*32:+32, :] ----
#pragma unroll
        for (int it = 0; it < 2; it++) {       // k16 steps over 32 ff
            int base = it * 8;
            unsigned a[4][4];
#pragma unroll
            for (int ms = 0; ms < 4; ms++) {
                int r = wm2 * 64 + ms * 16 + g;
                uint2 u = *reinterpret_cast<const uint2*>(&HSW[r * HPW + base + 2 * t]);
                uint2 v = *reinterpret_cast<const uint2*>(&HSW[(r + 8) * HPW + base + 2 * t]);
                a[ms][0] = u.x; a[ms][1] = v.x; a[ms][2] = u.y; a[ms][3] = v.y;
            }
#pragma unroll
            for (int ns = 0; ns < 8; ns++) {
                int n = wn4 * 64 + ns * 8 + g;
                uint2 bb = *reinterpret_cast<const uint2*>(&B2c[n * B2PW + base + 2 * t]);
#pragma unroll
                for (int ms = 0; ms < 4; ms++)
                    MMA16(y[ms][ns], a[ms], bb.x, bb.y);
            }
        }
    }

    // ---- epilogue: Y + b2 -> scatter to out[token] (GEMM2 tiling) ----
#pragma unroll
    for (int ms = 0; ms < 4; ms++) {
        int r = wm2 * 64 + ms * 16 + g;
        int tk0 = TOK[r], tk1 = TOK[r + 8];
#pragma unroll
        for (int ns = 0; ns < 8; ns++) {
            int col = wn4 * 64 + ns * 8 + 2 * t;
            float bb0 = BS2[col];
            float bb1 = BS2[col + 1];
            if (tk0 >= 0) {
                float2 v;
                v.x = y[ms][ns][0] + bb0;
                v.y = y[ms][ns][1] + bb1;
                *reinterpret_cast<float2*>(&out[(size_t)tk0 * DM + col]) = v;
            }
            if (tk1 >= 0) {
                float2 v;
                v.x = y[ms][ns][2] + bb0;
                v.y = y[ms][ns][3] + bb1;
                *reinterpret_cast<float2*>(&out[(size_t)tk1 * DM + col]) = v;
            }
        }
    }
}

// ---------------- launch ----------------

extern "C" void kernel_launch(void* const* d_in, const int* in_sizes, int n_in,
                              void* d_out, int out_size) {
    const float* x     = (const float*)d_in[0];
    const float* W1    = (const float*)d_in[1];
    const float* b1    = (const float*)d_in[2];
    const float* W2    = (const float*)d_in[3];
    const float* b2    = (const float*)d_in[4];
    const int*   b_seq = (const int*)d_in[5];
    float* out = (float*)d_out;

    cudaFuncSetAttribute(pff_main_k, cudaFuncAttributeMaxDynamicSharedMemorySize,
                         SM_BYTES);

    // 4 launches; pff_main_k at index 3 (confirmed ncu target)
    zero_inactive_cnt_k<<<NT / 8, 256>>>(b_seq, (float4*)out);
    build_lists_k<<<NT / 256, 256>>>(b_seq);
    prep_pack_k<<<(NE * 128 * DF + NE * 512 * DM + 255) / 256, 256>>>(W1, W2);
    pff_main_k<<<516, 256, SM_BYTES>>>(x, b1, b2, out);
}

// round 15
// speedup vs baseline: 1.1243x; 1.1243x over previous
#include <cuda_runtime.h>
#include <cuda_fp16.h>
#include <cstdint>

#define DM 256
#define DF 1024
#define NE 4
#define NT 65536
#define CH 64          // ff columns per chunk
#define NCH 16

// word (=4B=half2) pitches; pair-interleaved layouts make every operand
// fetch an LDS.64 with bank-pair pattern 4g+t (conflict-free per phase):
//  pitch/2 % 16 == 4  ->  136 and 40
#define XPW  136   // X  [128 r][128 kw]
#define B1PW 136   // B1 [64 n][128 kw]
#define B2PW 40    // B2 [256 n][32 kw]
#define HPW  40    // H  [128 r][32 kw]

// word offsets in dynamic smem
#define SM_XS  0                        // 128*136 = 17408
#define SM_B1  17408                    // 64*136  = 8704
#define SM_B2  26112                    // 256*40  = 10240
#define SM_HS  36352                    // 128*40  = 5120
#define SM_BS1 41472                    // 1024 fp32
#define SM_BS2 42496                    // 256 fp32
#define SM_TOK 42752                    // 128 int
#define SM_WORDS 42880
#define SM_BYTES (SM_WORDS * 4)         // 171520 bytes

__device__ int      g_cnt[NE];
__device__ int      g_list[NE * NT];
__device__ unsigned g_w1p[NE * DF * 128];  // [e][ff n][kw] pair-interleaved half2
__device__ unsigned g_w2p[NE * DM * 512];  // [e][dm n][kw] pair-interleaved half2

__device__ __forceinline__ unsigned f2h2(float lo, float hi) {
    __half2 h = __floats2half2_rn(lo, hi);
    return *reinterpret_cast<unsigned*>(&h);
}

__device__ __forceinline__ void cp16(void* s, const void* g) {
    uint32_t sa = (uint32_t)__cvta_generic_to_shared(s);
    asm volatile("cp.async.cg.shared.global [%0], [%1], 16;" :: "r"(sa), "l"(g));
}

#define CP_COMMIT() asm volatile("cp.async.commit_group;")
#define CP_WAIT0()  asm volatile("cp.async.wait_group 0;")

// D += A*B for m16n8k16 fp16 inputs, fp32 accumulate
#define MMA16(d, a, b0, b1)                                                  \
    asm volatile(                                                            \
        "mma.sync.aligned.m16n8k16.row.col.f32.f16.f16.f32 "                 \
        "{%0,%1,%2,%3},{%4,%5,%6,%7},{%8,%9},{%0,%1,%2,%3};"                 \
        : "+f"((d)[0]), "+f"((d)[1]), "+f"((d)[2]), "+f"((d)[3])             \
        : "r"((a)[0]), "r"((a)[1]), "r"((a)[2]), "r"((a)[3]),                \
          "r"(b0), "r"(b1))

// interleave map: q -> s = 2*(q&3) + (q>>2) within each 8-word block
__device__ __forceinline__ int smap(int w) {
    return (w & ~7) + 2 * (w & 3) + ((w & 7) >> 2);
}

// ---------------- prep kernels ----------------

// launch 0: zero inactive output rows + zero counters
__global__ void zero_inactive_cnt_k(const int* __restrict__ b_seq,
                                    float4* __restrict__ out4) {
    if (blockIdx.x == 0 && threadIdx.x < NE) g_cnt[threadIdx.x] = 0;
    int w = (blockIdx.x * blockDim.x + threadIdx.x) >> 5;
    int lane = threadIdx.x & 31;
    if (b_seq[w] == 0) {
        float4 z = make_float4(0.f, 0.f, 0.f, 0.f);
        out4[(size_t)w * 64 + lane] = z;
        out4[(size_t)w * 64 + 32 + lane] = z;
    }
}

// launch 1
__global__ void build_lists_k(const int* __restrict__ b_seq) {
    int t = blockIdx.x * blockDim.x + threadIdx.x;
    if (t < NT) {
        int b = b_seq[t];
        if (b > 0) {
            int p = atomicAdd(&g_cnt[b - 1], 1);
            g_list[(b - 1) * NT + p] = t;
        }
    }
}

// launch 2: pack W1/W2 -> half2, k-pair-interleaved, n-major rows
__global__ void prep_pack_k(const float* __restrict__ W1,
                            const float* __restrict__ W2) {
    int id = blockIdx.x * blockDim.x + threadIdx.x;
    const int N1 = NE * 128 * DF;            // w1 words
    if (id < N1) {
        int n = id % DF;
        int r = id / DF;
        int kpos = r % 128, e = r / 128;
        int s = kpos & 7;
        int kp = (kpos & ~7) + (s >> 1) + ((s & 1) << 2);
        const float* w1e = W1 + (size_t)e * DM * DF;
        float lo = w1e[(size_t)(2 * kp) * DF + n];
        float hi = w1e[(size_t)(2 * kp + 1) * DF + n];
        g_w1p[((size_t)e * DF + n) * 128 + kpos] = f2h2(lo, hi);
    } else {
        int id2 = id - N1;
        if (id2 < NE * 512 * DM) {
            int n = id2 % DM;
            int r = id2 / DM;
            int kpos = r % 512, e = r / 512;
            int s = kpos & 7;
            int kp = (kpos & ~7) + (s >> 1) + ((s & 1) << 2);
            const float* w2e = W2 + (size_t)e * DF * DM;
            float lo = w2e[(size_t)(2 * kp) * DM + n];
            float hi = w2e[(size_t)(2 * kp + 1) * DM + n];
            g_w2p[((size_t)e * DM + n) * 512 + kpos] = f2h2(lo, hi);
        }
    }
}

// ---------------- main fused grouped FFN kernel (launch 3) ----------------
// 1 CTA = 128 tokens of one expert, 256 threads = 8 warps. FP16 operands,
// fp32 accumulate, m16n8k16. Chunk = 64 ff: GEMM1 warp tile 32x32
// (loads/MMA = 1.0 vs 1.5 at chunk 32), 16 chunks x 2 syncs = 32 barriers.
// Single-buffered B1/B2; b2(fc) cp.asyncs interleaved into GEMM1(fc),
// b1(fc+1) interleaved into GEMM2(fc) -> each wait is wait_group 0 with
// exactly one outstanding group, loads overlap the MMA phases.

__global__ __launch_bounds__(256, 1)
void pff_main_k(const float* __restrict__ x,
                const float* __restrict__ b1g,
                const float* __restrict__ b2g,
                float* __restrict__ out) {
    extern __shared__ unsigned smw[];
    unsigned* XSW = smw + SM_XS;
    unsigned* B1W = smw + SM_B1;
    unsigned* B2W = smw + SM_B2;
    unsigned* HSW = smw + SM_HS;
    float*    BS1 = (float*)(smw + SM_BS1);
    float*    BS2 = (float*)(smw + SM_BS2);
    int*      TOK = (int*)(smw + SM_TOK);

    // resolve (expert, segment)
    int bid = blockIdx.x;
    int e = -1, seg = 0, cnt = 0, acc = 0;
#pragma unroll
    for (int i = 0; i < NE; i++) {
        int ci = g_cnt[i];
        int nt = (ci + 127) >> 7;
        if (e < 0 && bid < acc + nt) { e = i; seg = bid - acc; cnt = ci; }
        acc += nt;
    }
    if (e < 0) return;

    int tid = threadIdx.x;

    if (tid < 128) {
        int idx = seg * 128 + tid;
        TOK[tid] = (idx < cnt) ? g_list[e * NT + idx] : -1;
    }
    // biases into smem (fp32)
#pragma unroll
    for (int q = 0; q < 4; q++) BS1[q * 256 + tid] = b1g[e * DF + q * 256 + tid];
    BS2[tid] = b2g[e * DM + tid];
    __syncthreads();

    // gather X rows -> fp16, pair-interleaved; padded rows = 0
    for (int i = tid; i < 128 * 64; i += 256) {
        int r = i >> 6, c4 = i & 63;
        int tk = TOK[r];
        float4 v = make_float4(0.f, 0.f, 0.f, 0.f);
        if (tk >= 0) v = reinterpret_cast<const float4*>(x)[(size_t)tk * 64 + c4];
        int w0 = 2 * c4;
        XSW[r * XPW + smap(w0)]     = f2h2(v.x, v.y);
        XSW[r * XPW + smap(w0 + 1)] = f2h2(v.z, v.w);
    }

    const unsigned* w1p = g_w1p + (size_t)e * DF * 128;
    const unsigned* w2p = g_w2p + (size_t)e * DM * 512;

    int w = tid >> 5, lane = tid & 31;
    int wm = w & 3, wn = w >> 2;        // GEMM1: 4M x 2N (32r x 32n tiles)
    int wm2 = w & 1, wn4 = w >> 1;      // GEMM2: 2M x 4N
    int g = lane >> 2, t = lane & 3;

    // Y accumulator: per warp 64 rows x 64 cols -> y[4][8][4] = 128 regs
    float y[4][8][4];
#pragma unroll
    for (int ms = 0; ms < 4; ms++)
#pragma unroll
        for (int ns = 0; ns < 8; ns++)
#pragma unroll
            for (int q = 0; q < 4; q++) y[ms][ns][q] = 0.f;

    // preload B1(0): 64 n-rows x 128 words, 8 cps/thread
#pragma unroll
    for (int q = 0; q < 8; q++) {
        int i = q * 256 + tid;
        int n = i >> 5, j = i & 31;
        cp16(&B1W[n * B1PW + j * 4], w1p + (size_t)n * 128 + j * 4);
    }
    CP_COMMIT();

    for (int fc = 0; fc < NCH; fc++) {
        CP_WAIT0();            // B1(fc) landed (only outstanding group)
        __syncthreads();       // + X/H phases of prev chunk fully drained

        // ---- GEMM1 (32r x 32n/warp): H64 = X @ W1[:, fc*64:+64] ----
        // b2(fc) cp.asyncs interleaved (one per 2 its)
        float h[2][4][4];
#pragma unroll
        for (int ms = 0; ms < 2; ms++)
#pragma unroll
            for (int ns = 0; ns < 4; ns++)
#pragma unroll
                for (int q = 0; q < 4; q++) h[ms][ns][q] = 0.f;

#pragma unroll
        for (int it = 0; it < 16; it++) {      // k16 steps over K=256
            if ((it & 1) == 0) {               // 8 b2 cps spread over 16 its
                int i = (it >> 1) * 256 + tid;
                int n = i >> 3, j = i & 7;
                cp16(&B2W[n * B2PW + j * 4],
                     w2p + (size_t)n * 512 + fc * 32 + j * 4);
            }
            int base = it * 8;
            unsigned a[2][4];
#pragma unroll
            for (int ms = 0; ms < 2; ms++) {
                int r = wm * 32 + ms * 16 + g;
                uint2 u = *reinterpret_cast<const uint2*>(&XSW[r * XPW + base + 2 * t]);
                uint2 v = *reinterpret_cast<const uint2*>(&XSW[(r + 8) * XPW + base + 2 * t]);
                a[ms][0] = u.x; a[ms][1] = v.x; a[ms][2] = u.y; a[ms][3] = v.y;
            }
#pragma unroll
            for (int ns = 0; ns < 4; ns++) {
                int n = wn * 32 + ns * 8 + g;
                uint2 bb = *reinterpret_cast<const uint2*>(&B1W[n * B1PW + base + 2 * t]);
                MMA16(h[0][ns], a[0], bb.x, bb.y);
                MMA16(h[1][ns], a[1], bb.x, bb.y);
            }
        }
        CP_COMMIT();           // group: b2(fc)

        // ---- relu + b1 -> HS (fp16, pair-interleaved) ----
#pragma unroll
        for (int ms = 0; ms < 2; ms++) {
            int r = wm * 32 + ms * 16 + g;
#pragma unroll
            for (int ns = 0; ns < 4; ns++) {
                int col = wn * 32 + ns * 8 + 2 * t;
                float bb0 = BS1[fc * CH + col];
                float bb1 = BS1[fc * CH + col + 1];
                int pos = wn * 16 + (ns >> 1) * 8 + 2 * t + (ns & 1);
                HSW[r * HPW + pos] =
                    f2h2(fmaxf(h[ms][ns][0] + bb0, 0.f),
                         fmaxf(h[ms][ns][1] + bb1, 0.f));
                HSW[(r + 8) * HPW + pos] =
                    f2h2(fmaxf(h[ms][ns][2] + bb0, 0.f),
                         fmaxf(h[ms][ns][3] + bb1, 0.f));
            }
        }
        CP_WAIT0();            // b2(fc) landed
        __syncthreads();       // + H visible + all warps done reading B1(fc)

        // ---- GEMM2 (2M x 4N): Y += relu(H64) @ W2[fc*64:+64, :] ----
        // b1(fc+1) cp.asyncs interleaved (two per it)
        int fcn = (fc + 1 < NCH) ? fc + 1 : NCH - 1;   // clamped (unused tail)
#pragma unroll
        for (int it = 0; it < 4; it++) {       // k16 steps over 64 ff
#pragma unroll
            for (int c = 0; c < 2; c++) {      // 8 b1 cps over 4 its
                int i = (it * 2 + c) * 256 + tid;
                int n = i >> 5, j = i & 31;
                cp16(&B1W[n * B1PW + j * 4],
                     w1p + ((size_t)(fcn * CH + n)) * 128 + j * 4);
            }
            int base = it * 8;
            unsigned a[4][4];
#pragma unroll
            for (int ms = 0; ms < 4; ms++) {
                int r = wm2 * 64 + ms * 16 + g;
                uint2 u = *reinterpret_cast<const uint2*>(&HSW[r * HPW + base + 2 * t]);
                uint2 v = *reinterpret_cast<const uint2*>(&HSW[(r + 8) * HPW + base + 2 * t]);
                a[ms][0] = u.x; a[ms][1] = v.x; a[ms][2] = u.y; a[ms][3] = v.y;
            }
#pragma unroll
            for (int ns = 0; ns < 8; ns++) {
                int n = wn4 * 64 + ns * 8 + g;
                uint2 bb = *reinterpret_cast<const uint2*>(&B2W[n * B2PW + base + 2 * t]);
#pragma unroll
                for (int ms = 0; ms < 4; ms++)
                    MMA16(y[ms][ns], a[ms], bb.x, bb.y);
            }
        }
        CP_COMMIT();           // group: b1(fc+1)
    }
    CP_WAIT0();                // drain tail prefetch before exit

    // ---- epilogue: Y + b2 -> scatter to out[token] (GEMM2 tiling) ----
#pragma unroll
    for (int ms = 0; ms < 4; ms++) {
        int r = wm2 * 64 + ms * 16 + g;
        int tk0 = TOK[r], tk1 = TOK[r + 8];
#pragma unroll
        for (int ns = 0; ns < 8; ns++) {
            int col = wn4 * 64 + ns * 8 + 2 * t;
            float bb0 = BS2[col];
            float bb1 = BS2[col + 1];
            if (tk0 >= 0) {
                float2 v;
                v.x = y[ms][ns][0] + bb0;
                v.y = y[ms][ns][1] + bb1;
                *reinterpret_cast<float2*>(&out[(size_t)tk0 * DM + col]) = v;
            }
            if (tk1 >= 0) {
                float2 v;
                v.x = y[ms][ns][2] + bb0;
                v.y = y[ms][ns][3] + bb1;
                *reinterpret_cast<float2*>(&out[(size_t)tk1 * DM + col]) = v;
            }
        }
    }
}

// ---------------- launch ----------------

extern "C" void kernel_launch(void* const* d_in, const int* in_sizes, int n_in,
                              void* d_out, int out_size) {
    const float* x     = (const float*)d_in[0];
    const float* W1    = (const float*)d_in[1];
    const float* b1    = (const float*)d_in[2];
    const float* W2    = (const float*)d_in[3];
    const float* b2    = (const float*)d_in[4];
    const int*   b_seq = (const int*)d_in[5];
    float* out = (float*)d_out;

    cudaFuncSetAttribute(pff_main_k, cudaFuncAttributeMaxDynamicSharedMemorySize,
                         SM_BYTES);

    // 4 launches; pff_main_k at index 3 (confirmed ncu target)
    zero_inactive_cnt_k<<<NT / 8, 256>>>(b_seq, (float4*)out);
    build_lists_k<<<NT / 256, 256>>>(b_seq);
    prep_pack_k<<<(NE * 128 * DF + NE * 512 * DM + 255) / 256, 256>>>(W1, W2);
    pff_main_k<<<516, 256, SM_BYTES>>>(x, b1, b2, out);
}

// round 17
// speedup vs baseline: 1.1812x; 1.0506x over previous
#include <cuda_runtime.h>
#include <cuda_fp16.h>
#include <cstdint>

#define DM 256
#define DF 1024
#define NE 4
#define NT 65536
#define CH 64          // ff columns per chunk
#define NCH 16

// word (=4B=half2) pitches; pair-interleaved layouts make every operand
// fetch an LDS.64 with conflict-free bank patterns:
//  pitch/2 % 16 == 4  ->  136 and 40
#define XPW  136   // X  [128 r][128 kw]
#define B1PW 136   // B1 [64 n][128 kw]
#define B2PW 40    // B2 [256 n][32 kw]
#define HPW  40    // H  [128 r][32 kw]

// word offsets in dynamic smem
#define SM_XS  0                        // 128*136 = 17408
#define SM_B1  17408                    // 64*136  = 8704
#define SM_B2  26112                    // 256*40  = 10240
#define SM_HS  36352                    // 128*40  = 5120
#define SM_BS1 41472                    // 1024 fp32
#define SM_BS2 42496                    // 256 fp32
#define SM_TOK 42752                    // 128 int
#define SM_WORDS 42880
#define SM_BYTES (SM_WORDS * 4)         // 171520 bytes

__device__ int      g_cnt[NE];
__device__ int      g_list[NE * NT];
__device__ unsigned g_w1p[NE * DF * 128];  // [e][ff n][kw] pair-interleaved half2
__device__ unsigned g_w2p[NE * DM * 512];  // [e][dm n][kw] pair-interleaved half2

__device__ __forceinline__ unsigned f2h2(float lo, float hi) {
    __half2 h = __floats2half2_rn(lo, hi);
    return *reinterpret_cast<unsigned*>(&h);
}

__device__ __forceinline__ void cp16(void* s, const void* g) {
    uint32_t sa = (uint32_t)__cvta_generic_to_shared(s);
    asm volatile("cp.async.cg.shared.global [%0], [%1], 16;" :: "r"(sa), "l"(g));
}

#define CP_COMMIT() asm volatile("cp.async.commit_group;")
#define CP_WAIT0()  asm volatile("cp.async.wait_group 0;")

// D += A*B for m16n8k16 fp16 inputs, fp32 accumulate
#define MMA16(d, a, b0, b1)                                                  \
    asm volatile(                                                            \
        "mma.sync.aligned.m16n8k16.row.col.f32.f16.f16.f32 "                 \
        "{%0,%1,%2,%3},{%4,%5,%6,%7},{%8,%9},{%0,%1,%2,%3};"                 \
        : "+f"((d)[0]), "+f"((d)[1]), "+f"((d)[2]), "+f"((d)[3])             \
        : "r"((a)[0]), "r"((a)[1]), "r"((a)[2]), "r"((a)[3]),                \
          "r"(b0), "r"(b1))

// interleave map: q -> s = 2*(q&3) + (q>>2) within each 8-word block
__device__ __forceinline__ int smap(int w) {
    return (w & ~7) + 2 * (w & 3) + ((w & 7) >> 2);
}

// ---------------- prep kernels ----------------

// launch 0: zero inactive output rows + zero counters
__global__ void zero_inactive_cnt_k(const int* __restrict__ b_seq,
                                    float4* __restrict__ out4) {
    if (blockIdx.x == 0 && threadIdx.x < NE) g_cnt[threadIdx.x] = 0;
    int w = (blockIdx.x * blockDim.x + threadIdx.x) >> 5;
    int lane = threadIdx.x & 31;
    if (b_seq[w] == 0) {
        float4 z = make_float4(0.f, 0.f, 0.f, 0.f);
        out4[(size_t)w * 64 + lane] = z;
        out4[(size_t)w * 64 + 32 + lane] = z;
    }
}

// launch 1
__global__ void build_lists_k(const int* __restrict__ b_seq) {
    int t = blockIdx.x * blockDim.x + threadIdx.x;
    if (t < NT) {
        int b = b_seq[t];
        if (b > 0) {
            int p = atomicAdd(&g_cnt[b - 1], 1);
            g_list[(b - 1) * NT + p] = t;
        }
    }
}

// launch 2: pack W1/W2 -> half2, k-pair-interleaved, n-major rows
__global__ void prep_pack_k(const float* __restrict__ W1,
                            const float* __restrict__ W2) {
    int id = blockIdx.x * blockDim.x + threadIdx.x;
    const int N1 = NE * 128 * DF;            // w1 words
    if (id < N1) {
        int n = id % DF;
        int r = id / DF;
        int kpos = r % 128, e = r / 128;
        int s = kpos & 7;
        int kp = (kpos & ~7) + (s >> 1) + ((s & 1) << 2);
        const float* w1e = W1 + (size_t)e * DM * DF;
        float lo = w1e[(size_t)(2 * kp) * DF + n];
        float hi = w1e[(size_t)(2 * kp + 1) * DF + n];
        g_w1p[((size_t)e * DF + n) * 128 + kpos] = f2h2(lo, hi);
    } else {
        int id2 = id - N1;
        if (id2 < NE * 512 * DM) {
            int n = id2 % DM;
            int r = id2 / DM;
            int kpos = r % 512, e = r / 512;
            int s = kpos & 7;
            int kp = (kpos & ~7) + (s >> 1) + ((s & 1) << 2);
            const float* w2e = W2 + (size_t)e * DF * DM;
            float lo = w2e[(size_t)(2 * kp) * DM + n];
            float hi = w2e[(size_t)(2 * kp + 1) * DM + n];
            g_w2p[((size_t)e * DM + n) * 512 + kpos] = f2h2(lo, hi);
        }
    }
}

// ---------------- main fused grouped FFN kernel (launch 3) ----------------
// 1 CTA = 128 tokens of one expert, 512 threads = 16 warps (4 per SMSP for
// stall coverage; per-thread regs ~115 <= 128 budget). FP16, fp32 accum.
// Chunk = 64 ff. GEMM1 4M x 4N (32r x 16n/warp), GEMM2 4M x 4N
// (32r x 64n/warp, y[2][8][4] = 64 regs). Single-buffered B1/B2 with
// cp.asyncs interleaved into the MMA loops; 2 syncs per chunk.

__global__ __launch_bounds__(512)
void pff_main_k(const float* __restrict__ x,
                const float* __restrict__ b1g,
                const float* __restrict__ b2g,
                float* __restrict__ out) {
    extern __shared__ unsigned smw[];
    unsigned* XSW = smw + SM_XS;
    unsigned* B1W = smw + SM_B1;
    unsigned* B2W = smw + SM_B2;
    unsigned* HSW = smw + SM_HS;
    float*    BS1 = (float*)(smw + SM_BS1);
    float*    BS2 = (float*)(smw + SM_BS2);
    int*      TOK = (int*)(smw + SM_TOK);

    // resolve (expert, segment)
    int bid = blockIdx.x;
    int e = -1, seg = 0, cnt = 0, acc = 0;
#pragma unroll
    for (int i = 0; i < NE; i++) {
        int ci = g_cnt[i];
        int nt = (ci + 127) >> 7;
        if (e < 0 && bid < acc + nt) { e = i; seg = bid - acc; cnt = ci; }
        acc += nt;
    }
    if (e < 0) return;

    int tid = threadIdx.x;

    if (tid < 128) {
        int idx = seg * 128 + tid;
        TOK[tid] = (idx < cnt) ? g_list[e * NT + idx] : -1;
    }
    // biases into smem (fp32)
    BS1[tid] = b1g[e * DF + tid];
    BS1[512 + tid] = b1g[e * DF + 512 + tid];
    if (tid < 256) BS2[tid] = b2g[e * DM + tid];
    __syncthreads();

    // gather X rows -> fp16, pair-interleaved; padded rows = 0
    for (int i = tid; i < 128 * 64; i += 512) {
        int r = i >> 6, c4 = i & 63;
        int tk = TOK[r];
        float4 v = make_float4(0.f, 0.f, 0.f, 0.f);
        if (tk >= 0) v = reinterpret_cast<const float4*>(x)[(size_t)tk * 64 + c4];
        int w0 = 2 * c4;
        XSW[r * XPW + smap(w0)]     = f2h2(v.x, v.y);
        XSW[r * XPW + smap(w0 + 1)] = f2h2(v.z, v.w);
    }

    const unsigned* w1p = g_w1p + (size_t)e * DF * 128;
    const unsigned* w2p = g_w2p + (size_t)e * DM * 512;

    int w = tid >> 5, lane = tid & 31;
    int wm = w & 3, wn = w >> 2;        // GEMM1: 4M x 4N (32r x 16n tiles)
    int wm2 = w & 3, wn8 = w >> 2;      // GEMM2: 4M x 4N (32r x 64n tiles)
    int g = lane >> 2, t = lane & 3;

    // Y accumulator: per warp 32 rows x 64 cols -> y[2][8][4] = 64 regs
    float y[2][8][4];
#pragma unroll
    for (int ms = 0; ms < 2; ms++)
#pragma unroll
        for (int ns = 0; ns < 8; ns++)
#pragma unroll
            for (int q = 0; q < 4; q++) y[ms][ns][q] = 0.f;

    // preload B1(0): 64 n-rows x 128 words = 2048 cps, 4/thread
#pragma unroll
    for (int q = 0; q < 4; q++) {
        int i = q * 512 + tid;
        int n = i >> 5, j = i & 31;
        cp16(&B1W[n * B1PW + j * 4], w1p + (size_t)n * 128 + j * 4);
    }
    CP_COMMIT();

    for (int fc = 0; fc < NCH; fc++) {
        CP_WAIT0();            // B1(fc) landed (only outstanding group)
        __syncthreads();       // + prev chunk fully drained

        // ---- GEMM1 (32r x 16n/warp): H64 = X @ W1[:, fc*64:+64] ----
        // b2(fc) cp.asyncs interleaved (one per 4 its)
        float h[2][2][4];
#pragma unroll
        for (int ms = 0; ms < 2; ms++)
#pragma unroll
            for (int ns = 0; ns < 2; ns++)
#pragma unroll
                for (int q = 0; q < 4; q++) h[ms][ns][q] = 0.f;

#pragma unroll
        for (int it = 0; it < 16; it++) {      // k16 steps over K=256
            if ((it & 3) == 0) {               // 4 b2 cps spread over 16 its
                int i = (it >> 2) * 512 + tid;
                int n = i >> 3, j = i & 7;
                cp16(&B2W[n * B2PW + j * 4],
                     w2p + (size_t)n * 512 + fc * 32 + j * 4);
            }
            int base = it * 8;
            unsigned a[2][4];
#pragma unroll
            for (int ms = 0; ms < 2; ms++) {
                int r = wm * 32 + ms * 16 + g;
                uint2 u = *reinterpret_cast<const uint2*>(&XSW[r * XPW + base + 2 * t]);
                uint2 v = *reinterpret_cast<const uint2*>(&XSW[(r + 8) * XPW + base + 2 * t]);
                a[ms][0] = u.x; a[ms][1] = v.x; a[ms][2] = u.y; a[ms][3] = v.y;
            }
#pragma unroll
            for (int ns = 0; ns < 2; ns++) {
                int n = wn * 16 + ns * 8 + g;
                uint2 bb = *reinterpret_cast<const uint2*>(&B1W[n * B1PW + base + 2 * t]);
                MMA16(h[0][ns], a[0], bb.x, bb.y);
                MMA16(h[1][ns], a[1], bb.x, bb.y);
            }
        }
        CP_COMMIT();           // group: b2(fc)

        // ---- relu + b1 -> HS (fp16, pair-interleaved) ----
        // col = wn*16 + ns*8 + 2t -> word q = wn*8 + ns*4 + t (block wn,
        // in-block w = 4ns + t) -> stored pos = wn*8 + 2t + ns
#pragma unroll
        for (int ms = 0; ms < 2; ms++) {
            int r = wm * 32 + ms * 16 + g;
#pragma unroll
            for (int ns = 0; ns < 2; ns++) {
                int col = wn * 16 + ns * 8 + 2 * t;
                float bb0 = BS1[fc * CH + col];
                float bb1 = BS1[fc * CH + col + 1];
                int pos = wn * 8 + 2 * t + ns;
                HSW[r * HPW + pos] =
                    f2h2(fmaxf(h[ms][ns][0] + bb0, 0.f),
                         fmaxf(h[ms][ns][1] + bb1, 0.f));
                HSW[(r + 8) * HPW + pos] =
                    f2h2(fmaxf(h[ms][ns][2] + bb0, 0.f),
                         fmaxf(h[ms][ns][3] + bb1, 0.f));
            }
        }
        CP_WAIT0();            // b2(fc) landed
        __syncthreads();       // + H visible + all warps done with B1(fc)

        // ---- GEMM2 (32r x 64n/warp): Y += relu(H64) @ W2[fc*64:+64, :] ----
        // b1(fc+1) cp.asyncs interleaved (one per it)
        int fcn = (fc + 1 < NCH) ? fc + 1 : NCH - 1;   // clamped (unused tail)
#pragma unroll
        for (int it = 0; it < 4; it++) {       // k16 steps over 64 ff
            {
                int i = it * 512 + tid;
                int n = i >> 5, j = i & 31;
                cp16(&B1W[n * B1PW + j * 4],
                     w1p + ((size_t)(fcn * CH + n)) * 128 + j * 4);
            }
            int base = it * 8;
            unsigned a[2][4];
#pragma unroll
            for (int ms = 0; ms < 2; ms++) {
                int r = wm2 * 32 + ms * 16 + g;
                uint2 u = *reinterpret_cast<const uint2*>(&HSW[r * HPW + base + 2 * t]);
                uint2 v = *reinterpret_cast<const uint2*>(&HSW[(r + 8) * HPW + base + 2 * t]);
                a[ms][0] = u.x; a[ms][1] = v.x; a[ms][2] = u.y; a[ms][3] = v.y;
            }
#pragma unroll
            for (int ns = 0; ns < 8; ns++) {
                int n = wn8 * 64 + ns * 8 + g;
                uint2 bb = *reinterpret_cast<const uint2*>(&B2W[n * B2PW + base + 2 * t]);
                MMA16(y[0][ns], a[0], bb.x, bb.y);
                MMA16(y[1][ns], a[1], bb.x, bb.y);
            }
        }
        CP_COMMIT();           // group: b1(fc+1)
    }
    CP_WAIT0();                // drain tail prefetch before exit

    // ---- epilogue: Y + b2 -> scatter to out[token] (GEMM2 tiling) ----
#pragma unroll
    for (int ms = 0; ms < 2; ms++) {
        int r = wm2 * 32 + ms * 16 + g;
        int tk0 = TOK[r], tk1 = TOK[r + 8];
#pragma unroll
        for (int ns = 0; ns < 8; ns++) {
            int col = wn8 * 64 + ns * 8 + 2 * t;
            float bb0 = BS2[col];
            float bb1 = BS2[col + 1];
            if (tk0 >= 0) {
                float2 v;
                v.x = y[ms][ns][0] + bb0;
                v.y = y[ms][ns][1] + bb1;
                *reinterpret_cast<float2*>(&out[(size_t)tk0 * DM + col]) = v;
            }
            if (tk1 >= 0) {
                float2 v;
                v.x = y[ms][ns][2] + bb0;
                v.y = y[ms][ns][3] + bb1;
                *reinterpret_cast<float2*>(&out[(size_t)tk1 * DM + col]) = v;
            }
        }
    }
}

// ---------------- launch ----------------

extern "C" void kernel_launch(void* const* d_in, const int* in_sizes, int n_in,
                              void* d_out, int out_size) {
    const float* x     = (const float*)d_in[0];
    const float* W1    = (const float*)d_in[1];
    const float* b1    = (const float*)d_in[2];
    const float* W2    = (const float*)d_in[3];
    const float* b2    = (const float*)d_in[4];
    const int*   b_seq = (const int*)d_in[5];
    float* out = (float*)d_out;

    cudaFuncSetAttribute(pff_main_k, cudaFuncAttributeMaxDynamicSharedMemorySize,
                         SM_BYTES);

    // 4 launches; pff_main_k at index 3 (confirmed ncu target)
    zero_inactive_cnt_k<<<NT / 8, 256>>>(b_seq, (float4*)out);
    build_lists_k<<<NT / 256, 256>>>(b_seq);
    prep_pack_k<<<(NE * 128 * DF + NE * 512 * DM + 255) / 256, 256>>>(W1, W2);
    pff_main_k<<<516, 512, SM_BYTES>>>(x, b1, b2, out);
}